// round 16
// baseline (speedup 1.0000x reference)
#include <cuda_runtime.h>
#include <cstdint>

#define RKHS 20
#define OUTD 128
#define TILE 128   // rows per tile == threads per block

// ---------- cp.async helpers ----------
__device__ __forceinline__ void cp_async16(uint32_t saddr, const void* gptr) {
    asm volatile("cp.async.cg.shared.global [%0], [%1], 16;\n" :: "r"(saddr), "l"(gptr));
}
__device__ __forceinline__ void cp_async4(uint32_t saddr, const void* gptr) {
    asm volatile("cp.async.ca.shared.global [%0], [%1], 4;\n" :: "r"(saddr), "l"(gptr));
}
__device__ __forceinline__ void cp_commit() {
    asm volatile("cp.async.commit_group;\n");
}
template <int N>
__device__ __forceinline__ void cp_wait() {
    asm volatile("cp.async.wait_group %0;\n" :: "n"(N));
}

// Fast cos: Cody-Waite 2-term reduction by 2*pi, then MUFU cos (|r|<=pi).
__device__ __forceinline__ float fast_cos(float x) {
    const float INV_2PI   = 0.15915494309189535f;
    const float TWO_PI_HI = 6.28318548202514648f;
    const float TWO_PI_LO = -1.7484556e-7f;
    float k = rintf(x * INV_2PI);
    float r = fmaf(-k, TWO_PI_HI, x);
    r = fmaf(-k, TWO_PI_LO, r);
    return __cosf(r);
}

// Packed fp32x2 FMA (one issue, two FMAs).
__device__ __forceinline__ void ffma2(unsigned long long& acc,
                                      unsigned long long a,
                                      unsigned long long b) {
    asm("fma.rn.f32x2 %0, %1, %2, %3;" : "=l"(acc) : "l"(a), "l"(b), "l"(acc));
}
__device__ __forceinline__ float unpack_add(unsigned long long v) {
    unsigned lo, hi;
    asm("mov.b64 {%0,%1}, %2;" : "=r"(lo), "=r"(hi) : "l"(v));
    return __uint_as_float(lo) + __uint_as_float(hi);
}

// Double-buffered cp.async pipeline; phase B uses 2 cols/lane (2 warps/row)
// to halve weight registers (80 -> 40) and lift occupancy to ~7 blocks/SM.
__global__ __launch_bounds__(TILE, 7) void kde_time_encoder_kernel(
    const float* __restrict__ t_diff,
    const int* __restrict__ kde_idx,
    const int* __restrict__ kde_mask,
    const float* __restrict__ kde_table,
    const float* __restrict__ W_proj,
    const float* __restrict__ b_proj,
    const float* __restrict__ W_fb,
    const float* __restrict__ b_fb,
    float* __restrict__ out,
    int n)
{
    __shared__ __align__(16) float sk[2][TILE * RKHS];  // 2 x 10 KB
    __shared__ float st[2][TILE];
    __shared__ int   smk[2][TILE];

    const int tid   = threadIdx.x;
    const int lane  = tid & 31;
    const int wid   = tid >> 5;        // 4 warps
    const int half  = wid & 1;         // which 64-col half of the row
    const int pairw = wid >> 1;        // row-pair id (0..1)
    const int obase = half * 64 + lane * 2;   // this lane's 2 output columns

    // Pre-pack this lane's 2 weight rows: wp[j][i] = (w_j[2i], w_j[2i+1]).
    unsigned long long wp[2][RKHS / 2];
    unsigned long long bpp[2];
    float wf[2], bf[2];
#pragma unroll
    for (int j = 0; j < 2; j++) {
        const float* wrow = W_proj + (obase + j) * RKHS;
#pragma unroll
        for (int i = 0; i < RKHS / 2; i++) {
            unsigned lo = __float_as_uint(wrow[2 * i]);
            unsigned hi = __float_as_uint(wrow[2 * i + 1]);
            wp[j][i] = (unsigned long long)lo | ((unsigned long long)hi << 32);
        }
        bpp[j] = (unsigned long long)__float_as_uint(b_proj[obase + j]); // hi = 0
        wf[j] = W_fb[obase + j];
        bf[j] = b_fb[obase + j];
    }

    const int ntiles = (n + TILE - 1) / TILE;
    const int stride = gridDim.x;
    const int tile0  = blockIdx.x;

    auto stage = [&](int buf, int tile, int m, int idx) {
        const int row = tile * TILE + tid;
        smk[buf][tid] = (row < n) ? m : 0;
        if (row < n) {
            cp_async4((uint32_t)__cvta_generic_to_shared(&st[buf][tid]),
                      t_diff + row);
            if (m) {
                const float* g = kde_table + (size_t)idx * RKHS;
                uint32_t s = (uint32_t)__cvta_generic_to_shared(sk[buf] + tid * RKHS);
#pragma unroll
                for (int q = 0; q < 5; q++)
                    cp_async16(s + 16u * q, g + 4 * q);
            }
        }
        cp_commit();   // exactly one group per stage per thread
    };

    auto load_scalars = [&](int tile, int& m, int& idx) {
        m = 0; idx = 0;
        if (tile < ntiles) {
            const int row = tile * TILE + tid;
            if (row < n) {
                m   = kde_mask[row];
                idx = kde_idx[row];
            }
        }
    };

    // ---- Prologue ----
    if (tile0 >= ntiles) return;   // block-uniform
    int m_cur, idx_cur;
    load_scalars(tile0, m_cur, idx_cur);
    stage(0, tile0, m_cur, idx_cur);
    int m_nxt, idx_nxt;
    load_scalars(tile0 + stride, m_nxt, idx_nxt);

    int cur = 0;
    for (int tile = tile0; tile < ntiles; tile += stride) {
        const int nxt = tile + stride;
        const bool has_next = nxt < ntiles;

        if (has_next) {
            stage(cur ^ 1, nxt, m_nxt, idx_nxt);
            load_scalars(nxt + stride, m_nxt, idx_nxt);
            cp_wait<1>();
        } else {
            cp_wait<0>();
        }
        __syncthreads();

        // ---- compute tile from buf[cur]; warp-pair per row ----
        const int base  = tile * TILE;
        const int nrows = min(TILE, n - base);
        for (int r = pairw; r < nrows; r += 2) {
            float2 res;
            if (smk[cur][r]) {                 // warp-uniform branch
                const ulonglong2* kk =
                    reinterpret_cast<const ulonglong2*>(sk[cur] + r * RKHS);
                unsigned long long a0 = bpp[0], a1 = bpp[1];
#pragma unroll
                for (int q = 0; q < 5; q++) {
                    ulonglong2 kp = kk[q];     // LDS.128 broadcast, packed pairs
                    ffma2(a0, kp.x, wp[0][2 * q]);
                    ffma2(a1, kp.x, wp[1][2 * q]);
                    ffma2(a0, kp.y, wp[0][2 * q + 1]);
                    ffma2(a1, kp.y, wp[1][2 * q + 1]);
                }
                res.x = unpack_add(a0);
                res.y = unpack_add(a1);
            } else {
                float t = st[cur][r];
                res.x = fast_cos(fmaf(t, wf[0], bf[0]));
                res.y = fast_cos(fmaf(t, wf[1], bf[1]));
            }
            // Warp writes 256B contiguous (STG.64 per lane).
            __stcs(reinterpret_cast<float2*>(out) +
                       (size_t)(base + r) * (OUTD / 2) + (obase >> 1), res);
        }
        __syncthreads();   // readers done before buf[cur] restage
        cur ^= 1;
    }
}

extern "C" void kernel_launch(void* const* d_in, const int* in_sizes, int n_in,
                              void* d_out, int out_size)
{
    // metadata order: src, dst, t_diff, kde_idx, kde_mask, kde_table,
    //                 W_proj, b_proj, W_fb, b_fb
    const float* t_diff    = (const float*)d_in[2];
    const int*   kde_idx   = (const int*)d_in[3];
    const int*   kde_mask  = (const int*)d_in[4];
    const float* kde_table = (const float*)d_in[5];
    const float* W_proj    = (const float*)d_in[6];
    const float* b_proj    = (const float*)d_in[7];
    const float* W_fb      = (const float*)d_in[8];
    const float* b_fb      = (const float*)d_in[9];
    float*       out       = (float*)d_out;

    const int n = in_sizes[2];  // BATCH

    // 7 resident blocks/SM x 148 SMs = 1036 persistent blocks.
    kde_time_encoder_kernel<<<1036, TILE>>>(
        t_diff, kde_idx, kde_mask, kde_table, W_proj, b_proj, W_fb, b_fb, out, n);
}

// round 17
// speedup vs baseline: 1.2639x; 1.2639x over previous
#include <cuda_runtime.h>
#include <cstdint>

#define RKHS 20
#define OUTD 128
#define TILE 128   // rows per tile == threads per block
#define NBUF 3     // pipeline depth: stage 2 tiles ahead

// ---------- cp.async helpers ----------
__device__ __forceinline__ void cp_async16(uint32_t saddr, const void* gptr) {
    asm volatile("cp.async.cg.shared.global [%0], [%1], 16;\n" :: "r"(saddr), "l"(gptr));
}
__device__ __forceinline__ void cp_async4(uint32_t saddr, const void* gptr) {
    asm volatile("cp.async.ca.shared.global [%0], [%1], 4;\n" :: "r"(saddr), "l"(gptr));
}
__device__ __forceinline__ void cp_commit() {
    asm volatile("cp.async.commit_group;\n");
}
template <int N>
__device__ __forceinline__ void cp_wait() {
    asm volatile("cp.async.wait_group %0;\n" :: "n"(N));
}

// Fast cos: Cody-Waite 2-term reduction by 2*pi, then MUFU cos (|r|<=pi).
__device__ __forceinline__ float fast_cos(float x) {
    const float INV_2PI   = 0.15915494309189535f;
    const float TWO_PI_HI = 6.28318548202514648f;
    const float TWO_PI_LO = -1.7484556e-7f;
    float k = rintf(x * INV_2PI);
    float r = fmaf(-k, TWO_PI_HI, x);
    r = fmaf(-k, TWO_PI_LO, r);
    return __cosf(r);
}

// Packed fp32x2 FMA (one issue, two FMAs).
__device__ __forceinline__ void ffma2(unsigned long long& acc,
                                      unsigned long long a,
                                      unsigned long long b) {
    asm("fma.rn.f32x2 %0, %1, %2, %3;" : "=l"(acc) : "l"(a), "l"(b), "l"(acc));
}
__device__ __forceinline__ float unpack_add(unsigned long long v) {
    unsigned lo, hi;
    asm("mov.b64 {%0,%1}, %2;" : "=r"(lo), "=r"(hi) : "l"(v));   // reg-pair split: free
    return __uint_as_float(lo) + __uint_as_float(hi);
}

// Triple-buffered cp.async pipeline (2 tiles in flight), ONE barrier per tile.
// Compute: R11-proven shape — 1 warp/row, lane owns 4 cols, f32x2 k-parity
// packed matvec, one STG.128 per lane per row.
__global__ __launch_bounds__(TILE, 4) void kde_time_encoder_kernel(
    const float* __restrict__ t_diff,
    const int* __restrict__ kde_idx,
    const int* __restrict__ kde_mask,
    const float* __restrict__ kde_table,
    const float* __restrict__ W_proj,
    const float* __restrict__ b_proj,
    const float* __restrict__ W_fb,
    const float* __restrict__ b_fb,
    float* __restrict__ out,
    int n)
{
    __shared__ __align__(16) float sk[NBUF][TILE * RKHS];  // 3 x 10 KB
    __shared__ float st[NBUF][TILE];
    __shared__ int   smk[NBUF][TILE];

    const int tid   = threadIdx.x;
    const int lane  = tid & 31;
    const int wid   = tid >> 5;
    const int obase = lane * 4;

    // Pre-pack this lane's 4 weight rows: wp[j][i] = (w_j[2i], w_j[2i+1]).
    unsigned long long wp[4][RKHS / 2];
    unsigned long long bpp[4];
    float wf[4], bf[4];
#pragma unroll
    for (int j = 0; j < 4; j++) {
        const float* wrow = W_proj + (obase + j) * RKHS;
#pragma unroll
        for (int i = 0; i < RKHS / 2; i++) {
            unsigned lo = __float_as_uint(wrow[2 * i]);
            unsigned hi = __float_as_uint(wrow[2 * i + 1]);
            wp[j][i] = (unsigned long long)lo | ((unsigned long long)hi << 32);
        }
        bpp[j] = (unsigned long long)__float_as_uint(b_proj[obase + j]); // hi = 0
        wf[j] = W_fb[obase + j];
        bf[j] = b_fb[obase + j];
    }

    const int ntiles = (n + TILE - 1) / TILE;
    const int stride = gridDim.x;
    const int tile0  = blockIdx.x;

    // Stage tile into buf (guarded internally); ALWAYS commits one group.
    auto stage = [&](int buf, int tile, int m, int idx) {
        if (tile < ntiles) {
            const int row = tile * TILE + tid;
            smk[buf][tid] = (row < n) ? m : 0;
            if (row < n) {
                cp_async4((uint32_t)__cvta_generic_to_shared(&st[buf][tid]),
                          t_diff + row);
                if (m) {
                    const float* g = kde_table + (size_t)idx * RKHS;
                    uint32_t s = (uint32_t)__cvta_generic_to_shared(sk[buf] + tid * RKHS);
#pragma unroll
                    for (int q = 0; q < 5; q++)
                        cp_async16(s + 16u * q, g + 4 * q);
                }
            }
        }
        cp_commit();
    };

    auto load_scalars = [&](int tile, int& m, int& idx) {
        m = 0; idx = 0;
        if (tile < ntiles) {
            const int row = tile * TILE + tid;
            if (row < n) {
                m   = kde_mask[row];
                idx = kde_idx[row];
            }
        }
    };

    // ---- Prologue: stage tiles k=0 and k=1; prefetch scalars for k=2 ----
    if (tile0 >= ntiles) return;   // block-uniform
    int m0, i0, m1, i1;
    load_scalars(tile0,          m0, i0);
    load_scalars(tile0 + stride, m1, i1);
    stage(0, tile0,          m0, i0);   // group G0
    stage(1, tile0 + stride, m1, i1);   // group G1
    int m_nxt, idx_nxt;
    load_scalars(tile0 + 2 * stride, m_nxt, idx_nxt);

    int k = 0;
    for (int tile = tile0; tile < ntiles; tile += stride, k++) {
        const int cur = k % NBUF;

        cp_wait<1>();        // group G_k done (only G_{k+1} may pend)
        __syncthreads();     // publish buf[cur]; also: all warps finished
                             // computing buf[(k+2)%3] (at iter k-1) -> safe to restage

        // Stage tile k+2 into buf[(k+2)%3]; prefetch scalars for k+3.
        stage((k + 2) % NBUF, tile + 2 * stride, m_nxt, idx_nxt);
        load_scalars(tile + 3 * stride, m_nxt, idx_nxt);

        // ---- compute tile k from buf[cur]; warp per row ----
        const int base  = tile * TILE;
        const int nrows = min(TILE, n - base);
        for (int r = wid; r < nrows; r += 4) {
            float4 res;
            if (smk[cur][r]) {                 // warp-uniform branch
                const ulonglong2* kk =
                    reinterpret_cast<const ulonglong2*>(sk[cur] + r * RKHS);
                unsigned long long a0 = bpp[0], a1 = bpp[1], a2 = bpp[2], a3 = bpp[3];
#pragma unroll
                for (int q = 0; q < 5; q++) {
                    ulonglong2 kp = kk[q];     // LDS.128 broadcast, packed pairs
                    ffma2(a0, kp.x, wp[0][2 * q]);
                    ffma2(a1, kp.x, wp[1][2 * q]);
                    ffma2(a2, kp.x, wp[2][2 * q]);
                    ffma2(a3, kp.x, wp[3][2 * q]);
                    ffma2(a0, kp.y, wp[0][2 * q + 1]);
                    ffma2(a1, kp.y, wp[1][2 * q + 1]);
                    ffma2(a2, kp.y, wp[2][2 * q + 1]);
                    ffma2(a3, kp.y, wp[3][2 * q + 1]);
                }
                res.x = unpack_add(a0);
                res.y = unpack_add(a1);
                res.z = unpack_add(a2);
                res.w = unpack_add(a3);
            } else {
                float t = st[cur][r];
                res.x = fast_cos(fmaf(t, wf[0], bf[0]));
                res.y = fast_cos(fmaf(t, wf[1], bf[1]));
                res.z = fast_cos(fmaf(t, wf[2], bf[2]));
                res.w = fast_cos(fmaf(t, wf[3], bf[3]));
            }
            __stcs(reinterpret_cast<float4*>(out + (size_t)(base + r) * OUTD) + lane, res);
        }
    }
}

extern "C" void kernel_launch(void* const* d_in, const int* in_sizes, int n_in,
                              void* d_out, int out_size)
{
    // metadata order: src, dst, t_diff, kde_idx, kde_mask, kde_table,
    //                 W_proj, b_proj, W_fb, b_fb
    const float* t_diff    = (const float*)d_in[2];
    const int*   kde_idx   = (const int*)d_in[3];
    const int*   kde_mask  = (const int*)d_in[4];
    const float* kde_table = (const float*)d_in[5];
    const float* W_proj    = (const float*)d_in[6];
    const float* b_proj    = (const float*)d_in[7];
    const float* W_fb      = (const float*)d_in[8];
    const float* b_fb      = (const float*)d_in[9];
    float*       out       = (float*)d_out;

    const int n = in_sizes[2];  // BATCH

    // 4 resident blocks/SM x 148 SMs = 592 persistent blocks.
    kde_time_encoder_kernel<<<592, TILE>>>(
        t_diff, kde_idx, kde_mask, kde_table, W_proj, b_proj, W_fb, b_fb, out, n);
}